// round 15
// baseline (speedup 1.0000x reference)
#include <cuda_runtime.h>
#include <cuda_fp16.h>
#include <cstdint>

// ---------------- problem dims ----------------
#define NOBS   72000
#define M_PAD  72064
#define NB     9000
#define LMAX   8
#define DIM    256
#define HEADS  8
#define DHEAD  32
#define DEPTH  8
#define FF     1024
#define OUTD   2048
#define CL     512
#define KVW    4096

// ---------------- scratch ----------------
__device__ __half g_xh  [M_PAD * DIM];
__device__ __half g_qh  [M_PAD * DIM];
__device__ __half g_h2  [M_PAD * DIM];
__device__ __half g_ctxh[M_PAD * DIM];
__device__ __half g_lnh [M_PAD * DIM];
__device__ __half g_Oh  [M_PAD * DIM];
__device__ __half g_ffh [M_PAD * FF];
__device__ __half g_trxh[M_PAD * DIM];
__device__ __half g_kvh [(long)M_PAD * KVW];
__device__ float  g_trx [M_PAD * DIM];
__device__ __half g_wTh [7536640];
__device__ float  g_bkv [DEPTH * 512];
__device__ __half g_q0  [LMAX * DIM];
__device__ int    g_dest[M_PAD];
__device__ int    g_cnt [NB];

#define OFF_MLP  0
#define OFF_WQ   196608
#define OFF_WKV  720896
#define OFF_WO   1769472
#define OFF_W1   2293760
#define OFF_W2   4390912
#define OFF_PROJ 6488064

// ---------------- helpers ----------------
__device__ __forceinline__ uint32_t smem_u32(const void* p) {
    uint32_t a;
    asm("{ .reg .u64 t; cvta.to.shared.u64 t, %1; cvt.u32.u64 %0, t; }" : "=r"(a) : "l"(p));
    return a;
}
__device__ __forceinline__ float gelu_tanh(float x) {
    const float k0 = 0.7978845608028654f, k1 = 0.044715f;
    float t = k0 * (x + k1 * x * x * x);
    float th;
    asm("tanh.approx.f32 %0, %1;" : "=f"(th) : "f"(t));
    return 0.5f * x * (1.0f + th);
}
__device__ __forceinline__ void ldm_x4(uint32_t* r, uint32_t addr) {
    asm volatile("ldmatrix.sync.aligned.m8n8.x4.shared.b16 {%0,%1,%2,%3}, [%4];"
        : "=r"(r[0]), "=r"(r[1]), "=r"(r[2]), "=r"(r[3]) : "r"(addr));
}
__device__ __forceinline__ void mma_f16(float* d, const uint32_t* a, const uint32_t* b) {
    asm volatile("mma.sync.aligned.m16n8k16.row.col.f32.f16.f16.f32 "
        "{%0,%1,%2,%3}, {%4,%5,%6,%7}, {%8,%9}, {%0,%1,%2,%3};"
        : "+f"(d[0]), "+f"(d[1]), "+f"(d[2]), "+f"(d[3])
        : "r"(a[0]), "r"(a[1]), "r"(a[2]), "r"(a[3]), "r"(b[0]), "r"(b[1]));
}
__device__ __forceinline__ void cp16cg(uint32_t dst, const void* src) {
    asm volatile("cp.async.cg.shared.global [%0], [%1], 16;"
        :: "r"(dst), "l"(src) : "memory");
}
__device__ __forceinline__ void cp16ca(uint32_t dst, const void* src) {
    asm volatile("cp.async.ca.shared.global [%0], [%1], 16;"
        :: "r"(dst), "l"(src) : "memory");
}
#define CP_COMMIT() asm volatile("cp.async.commit_group;" ::: "memory")
#define CP_WAIT1()  asm volatile("cp.async.wait_group 1;" ::: "memory")
#define SWZ(off) ((off) ^ (((off) >> 3) & 0x70))

// ---------------- setup kernels ----------------
__global__ void zero_cnt_kernel(int* cnt) {
    int i = blockIdx.x * 256 + threadIdx.x;
    if (i < NB) cnt[i] = 0;
}
__global__ void dest_kernel(const int* __restrict__ li, int* __restrict__ cnt,
                            int* __restrict__ dest) {
    int i = blockIdx.x * 256 + threadIdx.x;
    if (i >= M_PAD) return;
    if (i >= NOBS) { dest[i] = i; return; }
    int f = li[3*i] * 1800 + li[3*i+1] * 60 + li[3*i+2];
    int slot = atomicAdd(&cnt[f], 1);
    dest[i] = f * LMAX + slot;
}
__global__ void init_trx_kernel(const float* __restrict__ bg, float* __restrict__ trx) {
    int tok = blockIdx.x & 7;
    trx[(long)blockIdx.x * DIM + threadIdx.x] = bg[tok * DIM + threadIdx.x];
}
__global__ void f2h_kernel(const float* __restrict__ in, __half* __restrict__ out, long n) {
    long i = ((long)blockIdx.x * 256 + threadIdx.x) * 4;
    if (i >= n) return;
    float4 v = *(const float4*)(in + i);
    *(__half2*)(out + i)     = __floats2half2_rn(v.x, v.y);
    *(__half2*)(out + i + 2) = __floats2half2_rn(v.z, v.w);
}
__global__ void bkv_kernel(const float* __restrict__ bk, const float* __restrict__ bv,
                           float* __restrict__ bkv) {
    int i = blockIdx.x * 256 + threadIdx.x;
    if (i >= DEPTH * 512) return;
    int l = i >> 9, c = i & 511;
    bkv[i] = (c < 256) ? bk[l * 256 + c] : bv[l * 256 + c - 256];
}

// layer-0 Q shortcut
__global__ void q0_kernel(const float* __restrict__ bg, const float* __restrict__ g,
                          const float* __restrict__ b, const __half* __restrict__ wqT0,
                          const float* __restrict__ bq0, __half* __restrict__ q0) {
    __shared__ float row[DIM];
    __shared__ float red[8];
    const int tok = blockIdx.x, tid = threadIdx.x;
    const int lane = tid & 31, wid = tid >> 5;
    float x = bg[tok * DIM + tid];
    float s = x;
#pragma unroll
    for (int o = 16; o; o >>= 1) s += __shfl_xor_sync(0xffffffffu, s, o);
    if (lane == 0) red[wid] = s;
    __syncthreads();
    if (wid == 0) {
        float t = (lane < 8) ? red[lane] : 0.f;
#pragma unroll
        for (int o = 4; o; o >>= 1) t += __shfl_xor_sync(0xffffffffu, t, o);
        if (lane == 0) red[0] = t;
    }
    __syncthreads();
    float mean = red[0] * (1.0f / DIM);
    float d = x - mean, vs = d * d;
#pragma unroll
    for (int o = 16; o; o >>= 1) vs += __shfl_xor_sync(0xffffffffu, vs, o);
    if (lane == 0) red[wid] = vs;
    __syncthreads();
    if (wid == 0) {
        float t = (lane < 8) ? red[lane] : 0.f;
#pragma unroll
        for (int o = 4; o; o >>= 1) t += __shfl_xor_sync(0xffffffffu, t, o);
        if (lane == 0) red[0] = t;
    }
    __syncthreads();
    float inv = rsqrtf(red[0] * (1.0f / DIM) + 1e-5f);
    row[tid] = __half2float(__float2half_rn(d * inv * g[tid] + b[tid]));
    __syncthreads();
    float acc = 0.f;
    const __half* wrow = wqT0 + tid * DIM;
#pragma unroll 8
    for (int k = 0; k < DIM; k++) acc += row[k] * __half2float(wrow[k]);
    q0[tok * DIM + tid] = __float2half_rn(acc + bq0[tid]);
}

// ---------------- single-launch fused weight transpose ----------------
__global__ __launch_bounds__(256)
void transpose_all(const float* __restrict__ mlp_w, const float* __restrict__ wq,
                   const float* __restrict__ wk,    const float* __restrict__ wv,
                   const float* __restrict__ wo,    const float* __restrict__ w1,
                   const float* __restrict__ w2,    const float* __restrict__ projw,
                   __half* __restrict__ wTh) {
    __shared__ float tile[32][33];
    const int tb = blockIdx.x;
    const float* src; __half* dst; int R, C, tiles_x, rem;
    if (tb < 192)       { int s=tb/64;        rem=tb%64;  src=mlp_w+s*65536;  dst=wTh+OFF_MLP+s*65536;  R=256;  C=256;  tiles_x=8;  }
    else if (tb < 704)  { int s=(tb-192)/64;  rem=(tb-192)%64;  src=wq+s*65536; dst=wTh+OFF_WQ+s*65536; R=256; C=256; tiles_x=8; }
    else if (tb < 1216) { int s=(tb-704)/64;  rem=(tb-704)%64;  src=wk+s*65536; dst=wTh+OFF_WKV+(long)s*131072;        R=256; C=256; tiles_x=8; }
    else if (tb < 1728) { int s=(tb-1216)/64; rem=(tb-1216)%64; src=wv+s*65536; dst=wTh+OFF_WKV+65536+(long)s*131072;  R=256; C=256; tiles_x=8; }
    else if (tb < 2240) { int s=(tb-1728)/64; rem=(tb-1728)%64; src=wo+s*65536; dst=wTh+OFF_WO+s*65536; R=256; C=256; tiles_x=8; }
    else if (tb < 4288) { int s=(tb-2240)/256; rem=(tb-2240)%256; src=w1+(long)s*262144; dst=wTh+OFF_W1+(long)s*262144; R=256;  C=1024; tiles_x=32; }
    else if (tb < 6336) { int s=(tb-4288)/256; rem=(tb-4288)%256; src=w2+(long)s*262144; dst=wTh+OFF_W2+(long)s*262144; R=1024; C=256;  tiles_x=8;  }
    else                { rem=tb-6336; src=projw; dst=wTh+OFF_PROJ; R=2048; C=512; tiles_x=16; }
    const int ty = rem / tiles_x, tx = rem % tiles_x;
    const int c0 = tx * 32, r0 = ty * 32;
    for (int i = threadIdx.y; i < 32; i += 8)
        tile[i][threadIdx.x] = src[(long)(r0 + i) * C + c0 + threadIdx.x];
    __syncthreads();
    for (int i = threadIdx.y; i < 32; i += 8)
        dst[(long)(c0 + i) * R + r0 + threadIdx.x] = __float2half_rn(tile[threadIdx.x][i]);
}

// ---------------- fp16 tensor-core GEMM (K-templated mainloop) ----------------
#define BM 128
#define BN 128
#define BKH 64
#define STG_BYTES 32768
#define GSMEM (3 * STG_BYTES)
#define EP_STRIDE 136

template<int KT, bool GELU, bool RES, bool F32O, bool HO, bool SCAT, bool GUARD>
__global__ __launch_bounds__(256, 2)
void gemm_h(const __half* __restrict__ A, const __half* __restrict__ Bt,
            const float* __restrict__ bias, float* __restrict__ C,
            __half* __restrict__ Ch, const int* __restrict__ rowmap,
            int M, int N) {
    extern __shared__ char smem[];
    const uint32_t sb = smem_u32(smem);
    const int tid = threadIdx.x;
    const int lane = tid & 31, wid = tid >> 5;
    const int warpM = wid >> 2, warpN = wid & 3;
    const int m0 = blockIdx.y * BM, n0 = blockIdx.x * BN;
    const int K = KT * BKH;

    float acc[4][4][4];
#pragma unroll
    for (int i = 0; i < 4; i++)
#pragma unroll
        for (int j = 0; j < 4; j++)
#pragma unroll
            for (int k = 0; k < 4; k++) acc[i][j][k] = 0.0f;

    const int lrow = tid >> 3, lcc = tid & 7;
    auto issue = [&](uint32_t abase, int kt) {
        const int kb = kt * BKH;
        const uint32_t bbase = abase + 16384;
        const __half* asrc = A + (long)(m0 + lrow) * K + kb + lcc * 8;
        const __half* bsrc = Bt + (long)(n0 + lrow) * K + kb + lcc * 8;
#pragma unroll
        for (int i = 0; i < 4; i++)
            cp16cg(abase + SWZ((lrow + 32 * i) * 128 + lcc * 16), asrc + (long)(32 * i) * K);
#pragma unroll
        for (int i = 0; i < 4; i++)
            cp16ca(bbase + SWZ((lrow + 32 * i) * 128 + lcc * 16), bsrc + (long)(32 * i) * K);
    };

    issue(sb, 0); CP_COMMIT();
    issue(sb + STG_BYTES, 1); CP_COMMIT();

    const int lm = lane >> 3, lr = lane & 7;

    auto step = [&](int kt, uint32_t abase) {
        const uint32_t bbase = abase + 16384;
#pragma unroll
        for (int ks = 0; ks < 4; ks++) {
            const int k0 = ks * 16;
            uint32_t afr[4][4], bfr[2][4];
#pragma unroll
            for (int mt = 0; mt < 4; mt++) {
                int row = warpM * 64 + mt * 16 + (lm & 1) * 8 + lr;
                int colh = k0 + (lm >> 1) * 8;
                ldm_x4(afr[mt], abase + SWZ(row * 128 + colh * 2));
            }
#pragma unroll
            for (int nt = 0; nt < 2; nt++) {
                int row = warpN * 32 + nt * 16 + (lm & 1) * 8 + lr;
                int colh = k0 + (lm >> 1) * 8;
                ldm_x4(bfr[nt], bbase + SWZ(row * 128 + colh * 2));
            }
#pragma unroll
            for (int mt = 0; mt < 4; mt++)
#pragma unroll
                for (int j = 0; j < 4; j++) {
                    uint32_t b2[2] = { bfr[j >> 1][j & 1], bfr[j >> 1][(j & 1) + 2] };
                    mma_f16(acc[mt][j], afr[mt], b2);
                }
        }
    };

    if (KT <= 4) {
        // small-K: fully unrolled mainloop, compile-time stage addresses
#pragma unroll
        for (int kt = 0; kt < KT; kt++) {
            const uint32_t cst = sb + (kt % 3) * STG_BYTES;
            CP_WAIT1();
            __syncthreads();
            if (kt + 2 < KT) issue(sb + ((kt + 2) % 3) * STG_BYTES, kt + 2);
            CP_COMMIT();
            step(kt, cst);
        }
    } else {
        // large-K: unroll 3 matches stage periodicity
#pragma unroll 3
        for (int kt = 0; kt < KT; kt++) {
            const uint32_t cst = sb + (kt % 3) * STG_BYTES;
            CP_WAIT1();
            __syncthreads();
            if (kt + 2 < KT) issue(sb + ((kt + 2) % 3) * STG_BYTES, kt + 2);
            CP_COMMIT();
            step(kt, cst);
        }
    }

    const int g = lane >> 2, t = lane & 3;
    __half* stg = (__half*)smem;
    if (HO) __syncthreads();

#pragma unroll
    for (int j = 0; j < 4; j++) {
        const int col = n0 + warpN * 32 + j * 8 + t * 2;
        const float bx = __ldg(&bias[col]), by = __ldg(&bias[col + 1]);
#pragma unroll
        for (int mt = 0; mt < 4; mt++) {
#pragma unroll
            for (int h = 0; h < 2; h++) {
                int lrowm = warpM * 64 + mt * 16 + g + h * 8;
                int row = m0 + lrowm;
                if (GUARD && row >= M) continue;
                float v0 = acc[mt][j][2 * h + 0] + bx;
                float v1 = acc[mt][j][2 * h + 1] + by;
                if (GELU) { v0 = gelu_tanh(v0); v1 = gelu_tanh(v1); }
                if (RES) {
                    int orow = SCAT ? rowmap[row] : row;
                    float2 r = *(const float2*)(C + (long)orow * N + col);
                    v0 += r.x; v1 += r.y;
                    if (F32O) {
                        float2 o; o.x = v0; o.y = v1;
                        *(float2*)(C + (long)orow * N + col) = o;
                    }
                } else if (F32O) {
                    int orow = SCAT ? rowmap[row] : row;
                    float2 o; o.x = v0; o.y = v1;
                    *(float2*)(C + (long)orow * N + col) = o;
                }
                if (HO)
                    *(__half2*)&stg[lrowm * EP_STRIDE + warpN * 32 + j * 8 + t * 2] =
                        __floats2half2_rn(v0, v1);
            }
        }
    }

    if (HO) {
        __syncthreads();
#pragma unroll
        for (int it = 0; it < 8; it++) {
            int job = it * 256 + tid;
            int row = job >> 4, chunk = job & 15;
            int grow = m0 + row;
            if (GUARD && grow >= M) continue;
            int orow = SCAT ? rowmap[grow] : grow;
            uint4 v = *(uint4*)&stg[row * EP_STRIDE + chunk * 8];
            *(uint4*)(Ch + (long)orow * N + n0 + chunk * 8) = v;
        }
    }
}

// ---------------- LayerNorm ----------------
__global__ void ln_kernel(const float* __restrict__ X, const float* __restrict__ g,
                          const float* __restrict__ b, __half* __restrict__ Y, int M) {
    int row = blockIdx.x * 8 + (threadIdx.x >> 5);
    int lane = threadIdx.x & 31;
    if (row >= M) return;
    const float* x = X + (long)row * DIM;
    float v[8], s = 0.f;
#pragma unroll
    for (int i = 0; i < 8; i++) { v[i] = x[lane + i * 32]; s += v[i]; }
#pragma unroll
    for (int o = 16; o; o >>= 1) s += __shfl_xor_sync(0xffffffffu, s, o);
    float mean = s * (1.0f / DIM), vs = 0.f;
#pragma unroll
    for (int i = 0; i < 8; i++) { float d = v[i] - mean; vs += d * d; }
#pragma unroll
    for (int o = 16; o; o >>= 1) vs += __shfl_xor_sync(0xffffffffu, vs, o);
    float inv = rsqrtf(vs * (1.0f / DIM) + 1e-5f);
    __half* y = Y + (long)row * DIM;
#pragma unroll
    for (int i = 0; i < 8; i++) {
        int c = lane + i * 32;
        y[c] = __float2half_rn((v[i] - mean) * inv * g[c] + b[c]);
    }
}

// ---------------- attention ----------------
#define ASTR 264
#define ATTN_SMEM (4 * 3 * 8 * ASTR * 2)

__global__ __launch_bounds__(256)
void attn_kernel(const __half* __restrict__ Q, long qb_stride,
                 const __half* __restrict__ KV, int koff,
                 __half* __restrict__ O) {
    extern __shared__ __half sm[];
    const int g = threadIdx.x >> 6;
    const int t = threadIdx.x & 63;
    const long b = (long)blockIdx.x * 4 + g;
    __half* Qs = sm + g * (3 * 8 * ASTR);
    __half* Ks = Qs + 8 * ASTR;
    __half* Vs = Ks + 8 * ASTR;
    const __half* qp  = Q + b * qb_stride;
    const __half* kvp = KV + b * 8 * KVW + koff;
#pragma unroll
    for (int i = t; i < 256; i += 64) {
        int r = i >> 5, c = (i & 31) * 8;
        *(uint4*)(Qs + r * ASTR + c) = *(const uint4*)(qp + r * 256 + c);
    }
#pragma unroll
    for (int i = t; i < 512; i += 64) {
        int r = i >> 6, c = (i & 63) * 8;
        __half* dst = (c < 256) ? (Ks + r * ASTR + c) : (Vs + r * ASTR + c - 256);
        *(uint4*)dst = *(const uint4*)(kvp + (long)r * KVW + c);
    }
    __syncthreads();
    const int q = t & 7, h = t >> 3, d0 = h * DHEAD;

    float qv[DHEAD];
    const __half2* qrow = (const __half2*)(Qs + q * ASTR + d0);
#pragma unroll
    for (int d2 = 0; d2 < 16; d2++) {
        float2 f = __half22float2(qrow[d2]);
        qv[2 * d2] = f.x; qv[2 * d2 + 1] = f.y;
    }
    float sc[8], mx = -1e30f;
#pragma unroll
    for (int k = 0; k < 8; k++) {
        const __half2* krow = (const __half2*)(Ks + k * ASTR + d0);
        float s = 0.f;
#pragma unroll
        for (int d2 = 0; d2 < 16; d2++) {
            float2 f = __half22float2(krow[d2]);
            s += qv[2 * d2] * f.x + qv[2 * d2 + 1] * f.y;
        }
        s *= 0.17677669529663687f;
        sc[k] = s; mx = fmaxf(mx, s);
    }
    float sum = 0.f;
#pragma unroll
    for (int k = 0; k < 8; k++) { sc[k] = __expf(sc[k] - mx); sum += sc[k]; }
    float inv = 1.0f / sum;
    float out[DHEAD];
#pragma unroll
    for (int d = 0; d < DHEAD; d++) out[d] = 0.f;
#pragma unroll
    for (int k = 0; k < 8; k++) {
        float p = sc[k] * inv;
        const __half2* vrow = (const __half2*)(Vs + k * ASTR + d0);
#pragma unroll
        for (int d2 = 0; d2 < 16; d2++) {
            float2 f = __half22float2(vrow[d2]);
            out[2 * d2]     += p * f.x;
            out[2 * d2 + 1] += p * f.y;
        }
    }
    __half2* op = (__half2*)(O + b * 2048 + q * 256 + d0);
#pragma unroll
    for (int d2 = 0; d2 < 16; d2++)
        op[d2] = __floats2half2_rn(out[2 * d2], out[2 * d2 + 1]);
}

// ---------------- host glue ----------------
static inline void launch_gemm(int mode, const __half* A, const __half* Bt, const float* bias,
                               float* C, __half* Ch, const int* rowmap, int M, int N, int K) {
    dim3 grid(N / BN, (M + BM - 1) / BM);
    if (K == 256) {
        switch (mode) {
        case 1: gemm_h<4, true,  false, false, true,  false, false><<<grid, 256, GSMEM>>>(A, Bt, bias, C, Ch, rowmap, M, N); break;
        case 2: gemm_h<4, false, true,  true,  false, false, false><<<grid, 256, GSMEM>>>(A, Bt, bias, C, Ch, rowmap, M, N); break;
        case 3: gemm_h<4, false, false, false, true,  false, false><<<grid, 256, GSMEM>>>(A, Bt, bias, C, Ch, rowmap, M, N); break;
        case 6: gemm_h<4, false, false, false, true,  true,  false><<<grid, 256, GSMEM>>>(A, Bt, bias, C, Ch, rowmap, M, N); break;
        }
    } else if (K == 1024) {
        switch (mode) {
        case 1: gemm_h<16, true,  false, false, true,  false, false><<<grid, 256, GSMEM>>>(A, Bt, bias, C, Ch, rowmap, M, N); break;
        case 2: gemm_h<16, false, true,  true,  false, false, false><<<grid, 256, GSMEM>>>(A, Bt, bias, C, Ch, rowmap, M, N); break;
        case 4: gemm_h<16, false, true,  true,  true,  false, false><<<grid, 256, GSMEM>>>(A, Bt, bias, C, Ch, rowmap, M, N); break;
        }
    } else {   // K == 2048
        gemm_h<32, false, false, true,  false, false, true ><<<grid, 256, GSMEM>>>(A, Bt, bias, C, Ch, rowmap, M, N);
    }
}

extern "C" void kernel_launch(void* const* d_in, const int* in_sizes, int n_in,
                              void* d_out, int out_size) {
    const float* x      = (const float*)d_in[0];
    const int*   linds  = (const int*)  d_in[1];
    const float* mlp_w  = (const float*)d_in[2];
    const float* mlp_b  = (const float*)d_in[3];
    const float* bg_tok = (const float*)d_in[4];
    const float* ln1_g  = (const float*)d_in[5];
    const float* ln1_b  = (const float*)d_in[6];
    const float* wq     = (const float*)d_in[7];
    const float* bq     = (const float*)d_in[8];
    const float* wk     = (const float*)d_in[9];
    const float* bk     = (const float*)d_in[10];
    const float* wv     = (const float*)d_in[11];
    const float* bv     = (const float*)d_in[12];
    const float* wo     = (const float*)d_in[13];
    const float* bo     = (const float*)d_in[14];
    const float* ln2_g  = (const float*)d_in[15];
    const float* ln2_b  = (const float*)d_in[16];
    const float* w1     = (const float*)d_in[17];
    const float* b1     = (const float*)d_in[18];
    const float* w2     = (const float*)d_in[19];
    const float* b2     = (const float*)d_in[20];
    const float* proj_w = (const float*)d_in[21];
    const float* proj_b = (const float*)d_in[22];
    float* out = (float*)d_out;

    __half *xh, *qh, *h2, *ctxh, *lnh, *Oh, *ffh, *trxh, *kvh, *wTh, *q0;
    float *trx, *bkv;
    int *dest, *cnt;
    cudaGetSymbolAddress((void**)&xh,   g_xh);
    cudaGetSymbolAddress((void**)&qh,   g_qh);
    cudaGetSymbolAddress((void**)&h2,   g_h2);
    cudaGetSymbolAddress((void**)&ctxh, g_ctxh);
    cudaGetSymbolAddress((void**)&lnh,  g_lnh);
    cudaGetSymbolAddress((void**)&Oh,   g_Oh);
    cudaGetSymbolAddress((void**)&ffh,  g_ffh);
    cudaGetSymbolAddress((void**)&trxh, g_trxh);
    cudaGetSymbolAddress((void**)&kvh,  g_kvh);
    cudaGetSymbolAddress((void**)&trx,  g_trx);
    cudaGetSymbolAddress((void**)&wTh,  g_wTh);
    cudaGetSymbolAddress((void**)&bkv,  g_bkv);
    cudaGetSymbolAddress((void**)&q0,   g_q0);
    cudaGetSymbolAddress((void**)&dest, g_dest);
    cudaGetSymbolAddress((void**)&cnt,  g_cnt);

    cudaFuncSetAttribute(gemm_h<4,  true,  false, false, true,  false, false>, cudaFuncAttributeMaxDynamicSharedMemorySize, GSMEM);
    cudaFuncSetAttribute(gemm_h<4,  false, true,  true,  false, false, false>, cudaFuncAttributeMaxDynamicSharedMemorySize, GSMEM);
    cudaFuncSetAttribute(gemm_h<4,  false, false, false, true,  false, false>, cudaFuncAttributeMaxDynamicSharedMemorySize, GSMEM);
    cudaFuncSetAttribute(gemm_h<4,  false, false, false, true,  true,  false>, cudaFuncAttributeMaxDynamicSharedMemorySize, GSMEM);
    cudaFuncSetAttribute(gemm_h<16, true,  false, false, true,  false, false>, cudaFuncAttributeMaxDynamicSharedMemorySize, GSMEM);
    cudaFuncSetAttribute(gemm_h<16, false, true,  true,  false, false, false>, cudaFuncAttributeMaxDynamicSharedMemorySize, GSMEM);
    cudaFuncSetAttribute(gemm_h<16, false, true,  true,  true,  false, false>, cudaFuncAttributeMaxDynamicSharedMemorySize, GSMEM);
    cudaFuncSetAttribute(gemm_h<32, false, false, true,  false, false, true >, cudaFuncAttributeMaxDynamicSharedMemorySize, GSMEM);
    cudaFuncSetAttribute(attn_kernel, cudaFuncAttributeMaxDynamicSharedMemorySize, ATTN_SMEM);

    transpose_all<<<7360, dim3(32, 8)>>>(mlp_w, wq, wk, wv, wo, w1, w2, proj_w, wTh);
    f2h_kernel<<<(NOBS * DIM / 4 + 255) / 256, 256>>>(x, xh, (long)NOBS * DIM);
    bkv_kernel<<<(DEPTH * 512 + 255) / 256, 256>>>(bk, bv, bkv);

    launch_gemm(1, xh, wTh + OFF_MLP + 0 * 65536, mlp_b + 0 * DIM, nullptr, qh, nullptr, M_PAD, DIM, DIM);
    launch_gemm(1, qh, wTh + OFF_MLP + 1 * 65536, mlp_b + 1 * DIM, nullptr, h2, nullptr, M_PAD, DIM, DIM);

    zero_cnt_kernel<<<(NB + 255) / 256, 256>>>(cnt);
    dest_kernel<<<(M_PAD + 255) / 256, 256>>>(linds, cnt, dest);
    launch_gemm(6, h2, wTh + OFF_MLP + 2 * 65536, mlp_b + 2 * DIM, nullptr, ctxh, dest, M_PAD, DIM, DIM);

    init_trx_kernel<<<NOBS, DIM>>>(bg_tok, trx);
    q0_kernel<<<LMAX, DIM>>>(bg_tok, ln1_g, ln1_b, wTh + OFF_WQ, bq, q0);

    launch_gemm(3, ctxh, wTh + OFF_WKV, bkv, nullptr, kvh, nullptr, M_PAD, KVW, DIM);

    for (int l = 0; l < DEPTH; l++) {
        const long o256 = (long)l * 65536;
        if (l == 0) {
            attn_kernel<<<NB / 4, 256, ATTN_SMEM>>>(q0, 0, kvh, 0, Oh);
        } else {
            ln_kernel<<<NOBS / 8, 256>>>(trx, ln1_g + l * DIM, ln1_b + l * DIM, lnh, NOBS);
            launch_gemm(3, lnh, wTh + OFF_WQ + o256, bq + l * DIM, nullptr, qh, nullptr, M_PAD, DIM, DIM);
            attn_kernel<<<NB / 4, 256, ATTN_SMEM>>>(qh, 2048, kvh, l * 512, Oh);
        }
        launch_gemm(2, Oh, wTh + OFF_WO + o256, bo + l * DIM, trx, nullptr, nullptr, M_PAD, DIM, DIM);
        ln_kernel<<<NOBS / 8, 256>>>(trx, ln2_g + l * DIM, ln2_b + l * DIM, lnh, NOBS);
        launch_gemm(1, lnh, wTh + OFF_W1 + (long)l * 262144, b1 + l * FF, nullptr, ffh, nullptr, M_PAD, FF, DIM);
        if (l < DEPTH - 1)
            launch_gemm(2, ffh, wTh + OFF_W2 + (long)l * 262144, b2 + l * DIM, trx, nullptr, nullptr, M_PAD, DIM, FF);
        else
            launch_gemm(4, ffh, wTh + OFF_W2 + (long)l * 262144, b2 + l * DIM, trx, trxh, nullptr, M_PAD, DIM, FF);
    }

    launch_gemm(5, trxh, wTh + OFF_PROJ, proj_b, out, nullptr, nullptr, NB, CL, OUTD);
}

// round 16
// speedup vs baseline: 1.0187x; 1.0187x over previous
#include <cuda_runtime.h>
#include <cuda_fp16.h>
#include <cstdint>

// ---------------- problem dims ----------------
#define NOBS   72000
#define M_PAD  72064
#define NB     9000
#define LMAX   8
#define DIM    256
#define HEADS  8
#define DHEAD  32
#define DEPTH  8
#define FF     1024
#define OUTD   2048
#define CL     512
#define KVW    4096

// ---------------- scratch ----------------
__device__ __half g_xh  [M_PAD * DIM];
__device__ __half g_qh  [M_PAD * DIM];
__device__ __half g_h2  [M_PAD * DIM];
__device__ __half g_ctxh[M_PAD * DIM];
__device__ __half g_lnh [M_PAD * DIM];
__device__ __half g_Oh  [M_PAD * DIM];
__device__ __half g_ffh [M_PAD * FF];
__device__ __half g_trxh[M_PAD * DIM];
__device__ __half g_kvh [(long)M_PAD * KVW];
__device__ float  g_trx [M_PAD * DIM];
__device__ __half g_wTh [7536640];
__device__ float  g_bkv [DEPTH * 512];
__device__ __half g_q0  [LMAX * DIM];
__device__ int    g_dest[M_PAD];
__device__ int    g_cnt [NB];

#define OFF_MLP  0
#define OFF_WQ   196608
#define OFF_WKV  720896
#define OFF_WO   1769472
#define OFF_W1   2293760
#define OFF_W2   4390912
#define OFF_PROJ 6488064

// ---------------- helpers ----------------
__device__ __forceinline__ uint32_t smem_u32(const void* p) {
    uint32_t a;
    asm("{ .reg .u64 t; cvta.to.shared.u64 t, %1; cvt.u32.u64 %0, t; }" : "=r"(a) : "l"(p));
    return a;
}
__device__ __forceinline__ float gelu_tanh(float x) {
    const float k0 = 0.7978845608028654f, k1 = 0.044715f;
    float t = k0 * (x + k1 * x * x * x);
    float th;
    asm("tanh.approx.f32 %0, %1;" : "=f"(th) : "f"(t));
    return 0.5f * x * (1.0f + th);
}
__device__ __forceinline__ void ldm_x4(uint32_t* r, uint32_t addr) {
    asm volatile("ldmatrix.sync.aligned.m8n8.x4.shared.b16 {%0,%1,%2,%3}, [%4];"
        : "=r"(r[0]), "=r"(r[1]), "=r"(r[2]), "=r"(r[3]) : "r"(addr));
}
__device__ __forceinline__ void mma_f16(float* d, const uint32_t* a, const uint32_t* b) {
    asm volatile("mma.sync.aligned.m16n8k16.row.col.f32.f16.f16.f32 "
        "{%0,%1,%2,%3}, {%4,%5,%6,%7}, {%8,%9}, {%0,%1,%2,%3};"
        : "+f"(d[0]), "+f"(d[1]), "+f"(d[2]), "+f"(d[3])
        : "r"(a[0]), "r"(a[1]), "r"(a[2]), "r"(a[3]), "r"(b[0]), "r"(b[1]));
}
__device__ __forceinline__ void cp16(uint32_t dst, const void* src) {
    asm volatile("cp.async.cg.shared.global [%0], [%1], 16;"
        :: "r"(dst), "l"(src) : "memory");
}
#define CP_COMMIT() asm volatile("cp.async.commit_group;" ::: "memory")
#define CP_WAIT1()  asm volatile("cp.async.wait_group 1;" ::: "memory")
#define SWZ(off) ((off) ^ (((off) >> 3) & 0x70))

// ---------------- setup kernels ----------------
__global__ void zero_cnt_kernel(int* cnt) {
    int i = blockIdx.x * 256 + threadIdx.x;
    if (i < NB) cnt[i] = 0;
}
__global__ void dest_kernel(const int* __restrict__ li, int* __restrict__ cnt,
                            int* __restrict__ dest) {
    int i = blockIdx.x * 256 + threadIdx.x;
    if (i >= M_PAD) return;
    if (i >= NOBS) { dest[i] = i; return; }
    int f = li[3*i] * 1800 + li[3*i+1] * 60 + li[3*i+2];
    int slot = atomicAdd(&cnt[f], 1);
    dest[i] = f * LMAX + slot;
}
__global__ void init_trx_kernel(const float* __restrict__ bg, float* __restrict__ trx) {
    int tok = blockIdx.x & 7;
    trx[(long)blockIdx.x * DIM + threadIdx.x] = bg[tok * DIM + threadIdx.x];
}
__global__ void f2h_kernel(const float* __restrict__ in, __half* __restrict__ out, long n) {
    long i = ((long)blockIdx.x * 256 + threadIdx.x) * 4;
    if (i >= n) return;
    float4 v = *(const float4*)(in + i);
    *(__half2*)(out + i)     = __floats2half2_rn(v.x, v.y);
    *(__half2*)(out + i + 2) = __floats2half2_rn(v.z, v.w);
}
__global__ void bkv_kernel(const float* __restrict__ bk, const float* __restrict__ bv,
                           float* __restrict__ bkv) {
    int i = blockIdx.x * 256 + threadIdx.x;
    if (i >= DEPTH * 512) return;
    int l = i >> 9, c = i & 511;
    bkv[i] = (c < 256) ? bk[l * 256 + c] : bv[l * 256 + c - 256];
}

// layer-0 Q shortcut
__global__ void q0_kernel(const float* __restrict__ bg, const float* __restrict__ g,
                          const float* __restrict__ b, const __half* __restrict__ wqT0,
                          const float* __restrict__ bq0, __half* __restrict__ q0) {
    __shared__ float row[DIM];
    __shared__ float red[8];
    const int tok = blockIdx.x, tid = threadIdx.x;
    const int lane = tid & 31, wid = tid >> 5;
    float x = bg[tok * DIM + tid];
    float s = x;
#pragma unroll
    for (int o = 16; o; o >>= 1) s += __shfl_xor_sync(0xffffffffu, s, o);
    if (lane == 0) red[wid] = s;
    __syncthreads();
    if (wid == 0) {
        float t = (lane < 8) ? red[lane] : 0.f;
#pragma unroll
        for (int o = 4; o; o >>= 1) t += __shfl_xor_sync(0xffffffffu, t, o);
        if (lane == 0) red[0] = t;
    }
    __syncthreads();
    float mean = red[0] * (1.0f / DIM);
    float d = x - mean, vs = d * d;
#pragma unroll
    for (int o = 16; o; o >>= 1) vs += __shfl_xor_sync(0xffffffffu, vs, o);
    if (lane == 0) red[wid] = vs;
    __syncthreads();
    if (wid == 0) {
        float t = (lane < 8) ? red[lane] : 0.f;
#pragma unroll
        for (int o = 4; o; o >>= 1) t += __shfl_xor_sync(0xffffffffu, t, o);
        if (lane == 0) red[0] = t;
    }
    __syncthreads();
    float inv = rsqrtf(red[0] * (1.0f / DIM) + 1e-5f);
    row[tid] = __half2float(__float2half_rn(d * inv * g[tid] + b[tid]));
    __syncthreads();
    float acc = 0.f;
    const __half* wrow = wqT0 + tid * DIM;
#pragma unroll 8
    for (int k = 0; k < DIM; k++) acc += row[k] * __half2float(wrow[k]);
    q0[tok * DIM + tid] = __float2half_rn(acc + bq0[tid]);
}

// ---------------- single-launch fused weight transpose ----------------
__global__ __launch_bounds__(256)
void transpose_all(const float* __restrict__ mlp_w, const float* __restrict__ wq,
                   const float* __restrict__ wk,    const float* __restrict__ wv,
                   const float* __restrict__ wo,    const float* __restrict__ w1,
                   const float* __restrict__ w2,    const float* __restrict__ projw,
                   __half* __restrict__ wTh) {
    __shared__ float tile[32][33];
    const int tb = blockIdx.x;
    const float* src; __half* dst; int R, C, tiles_x, rem;
    if (tb < 192)       { int s=tb/64;        rem=tb%64;  src=mlp_w+s*65536;  dst=wTh+OFF_MLP+s*65536;  R=256;  C=256;  tiles_x=8;  }
    else if (tb < 704)  { int s=(tb-192)/64;  rem=(tb-192)%64;  src=wq+s*65536; dst=wTh+OFF_WQ+s*65536; R=256; C=256; tiles_x=8; }
    else if (tb < 1216) { int s=(tb-704)/64;  rem=(tb-704)%64;  src=wk+s*65536; dst=wTh+OFF_WKV+(long)s*131072;        R=256; C=256; tiles_x=8; }
    else if (tb < 1728) { int s=(tb-1216)/64; rem=(tb-1216)%64; src=wv+s*65536; dst=wTh+OFF_WKV+65536+(long)s*131072;  R=256; C=256; tiles_x=8; }
    else if (tb < 2240) { int s=(tb-1728)/64; rem=(tb-1728)%64; src=wo+s*65536; dst=wTh+OFF_WO+s*65536; R=256; C=256; tiles_x=8; }
    else if (tb < 4288) { int s=(tb-2240)/256; rem=(tb-2240)%256; src=w1+(long)s*262144; dst=wTh+OFF_W1+(long)s*262144; R=256;  C=1024; tiles_x=32; }
    else if (tb < 6336) { int s=(tb-4288)/256; rem=(tb-4288)%256; src=w2+(long)s*262144; dst=wTh+OFF_W2+(long)s*262144; R=1024; C=256;  tiles_x=8;  }
    else                { rem=tb-6336; src=projw; dst=wTh+OFF_PROJ; R=2048; C=512; tiles_x=16; }
    const int ty = rem / tiles_x, tx = rem % tiles_x;
    const int c0 = tx * 32, r0 = ty * 32;
    for (int i = threadIdx.y; i < 32; i += 8)
        tile[i][threadIdx.x] = src[(long)(r0 + i) * C + c0 + threadIdx.x];
    __syncthreads();
    for (int i = threadIdx.y; i < 32; i += 8)
        dst[(long)(c0 + i) * R + r0 + threadIdx.x] = __float2half_rn(tile[threadIdx.x][i]);
}

// ---------------- fp16 tensor-core GEMM (R14: proven best config) ----------------
#define BM 128
#define BN 128
#define BKH 64
#define STG_BYTES 32768
#define GSMEM (3 * STG_BYTES)
#define EP_STRIDE 136

template<bool GELU, bool RES, bool F32O, bool HO, bool SCAT, bool GUARD>
__global__ __launch_bounds__(256, 2)
void gemm_h(const __half* __restrict__ A, const __half* __restrict__ Bt,
            const float* __restrict__ bias, float* __restrict__ C,
            __half* __restrict__ Ch, const int* __restrict__ rowmap,
            int M, int N, int K) {
    extern __shared__ char smem[];
    const uint32_t sb = smem_u32(smem);
    const int tid = threadIdx.x;
    const int lane = tid & 31, wid = tid >> 5;
    const int warpM = wid >> 2, warpN = wid & 3;
    const int m0 = blockIdx.y * BM, n0 = blockIdx.x * BN;
    const int ntiles = K / BKH;

    float acc[4][4][4];
#pragma unroll
    for (int i = 0; i < 4; i++)
#pragma unroll
        for (int j = 0; j < 4; j++)
#pragma unroll
            for (int k = 0; k < 4; k++) acc[i][j][k] = 0.0f;

    const int lrow = tid >> 3, lcc = tid & 7;
    auto issue = [&](uint32_t abase, int kt) {
        const int kb = kt * BKH;
        const uint32_t bbase = abase + 16384;
        const __half* asrc = A + (long)(m0 + lrow) * K + kb + lcc * 8;
        const __half* bsrc = Bt + (long)(n0 + lrow) * K + kb + lcc * 8;
#pragma unroll
        for (int i = 0; i < 4; i++)
            cp16(abase + SWZ((lrow + 32 * i) * 128 + lcc * 16), asrc + (long)(32 * i) * K);
#pragma unroll
        for (int i = 0; i < 4; i++)
            cp16(bbase + SWZ((lrow + 32 * i) * 128 + lcc * 16), bsrc + (long)(32 * i) * K);
    };

    issue(sb, 0); CP_COMMIT();
    issue(sb + STG_BYTES, 1); CP_COMMIT();

    const int lm = lane >> 3, lr = lane & 7;

    uint32_t cstage = sb;
    uint32_t istage = sb + 2 * STG_BYTES;
    for (int kt = 0; kt < ntiles; kt++) {
        CP_WAIT1();
        __syncthreads();
        if (kt + 2 < ntiles) issue(istage, kt + 2);
        CP_COMMIT();
        const uint32_t abase = cstage;
        const uint32_t bbase = cstage + 16384;
        istage = cstage;
        cstage = (cstage == sb + 2 * STG_BYTES) ? sb : cstage + STG_BYTES;
#pragma unroll
        for (int ks = 0; ks < 4; ks++) {
            const int k0 = ks * 16;
            uint32_t afr[4][4], bfr[2][4];
#pragma unroll
            for (int mt = 0; mt < 4; mt++) {
                int row = warpM * 64 + mt * 16 + (lm & 1) * 8 + lr;
                int colh = k0 + (lm >> 1) * 8;
                ldm_x4(afr[mt], abase + SWZ(row * 128 + colh * 2));
            }
#pragma unroll
            for (int nt = 0; nt < 2; nt++) {
                int row = warpN * 32 + nt * 16 + (lm & 1) * 8 + lr;
                int colh = k0 + (lm >> 1) * 8;
                ldm_x4(bfr[nt], bbase + SWZ(row * 128 + colh * 2));
            }
#pragma unroll
            for (int mt = 0; mt < 4; mt++)
#pragma unroll
                for (int j = 0; j < 4; j++) {
                    uint32_t b2[2] = { bfr[j >> 1][j & 1], bfr[j >> 1][(j & 1) + 2] };
                    mma_f16(acc[mt][j], afr[mt], b2);
                }
        }
    }

    const int g = lane >> 2, t = lane & 3;
    __half* stg = (__half*)smem;
    if (HO) __syncthreads();

#pragma unroll
    for (int j = 0; j < 4; j++) {
        const int col = n0 + warpN * 32 + j * 8 + t * 2;
        const float bx = __ldg(&bias[col]), by = __ldg(&bias[col + 1]);
#pragma unroll
        for (int mt = 0; mt < 4; mt++) {
#pragma unroll
            for (int h = 0; h < 2; h++) {
                int lrowm = warpM * 64 + mt * 16 + g + h * 8;
                int row = m0 + lrowm;
                if (GUARD && row >= M) continue;
                float v0 = acc[mt][j][2 * h + 0] + bx;
                float v1 = acc[mt][j][2 * h + 1] + by;
                if (GELU) { v0 = gelu_tanh(v0); v1 = gelu_tanh(v1); }
                if (RES) {
                    int orow = SCAT ? rowmap[row] : row;
                    float2 r = *(const float2*)(C + (long)orow * N + col);
                    v0 += r.x; v1 += r.y;
                    if (F32O) {
                        float2 o; o.x = v0; o.y = v1;
                        *(float2*)(C + (long)orow * N + col) = o;
                    }
                } else if (F32O) {
                    int orow = SCAT ? rowmap[row] : row;
                    float2 o; o.x = v0; o.y = v1;
                    *(float2*)(C + (long)orow * N + col) = o;
                }
                if (HO)
                    *(__half2*)&stg[lrowm * EP_STRIDE + warpN * 32 + j * 8 + t * 2] =
                        __floats2half2_rn(v0, v1);
            }
        }
    }

    if (HO) {
        __syncthreads();
#pragma unroll
        for (int it = 0; it < 8; it++) {
            int job = it * 256 + tid;
            int row = job >> 4, chunk = job & 15;
            int grow = m0 + row;
            if (GUARD && grow >= M) continue;
            int orow = SCAT ? rowmap[grow] : grow;
            uint4 v = *(uint4*)&stg[row * EP_STRIDE + chunk * 8];
            *(uint4*)(Ch + (long)orow * N + n0 + chunk * 8) = v;
        }
    }
}

// ---------------- LayerNorm: vectorized (lane owns 8 consecutive cols) ----------------
__global__ void ln_kernel(const float* __restrict__ X, const float* __restrict__ g,
                          const float* __restrict__ b, __half* __restrict__ Y, int M) {
    int row = blockIdx.x * 8 + (threadIdx.x >> 5);
    int lane = threadIdx.x & 31;
    if (row >= M) return;
    const float4* x4 = (const float4*)(X + (long)row * DIM) + lane * 2;
    float4 f0 = x4[0], f1 = x4[1];
    float s = f0.x + f0.y + f0.z + f0.w + f1.x + f1.y + f1.z + f1.w;
#pragma unroll
    for (int o = 16; o; o >>= 1) s += __shfl_xor_sync(0xffffffffu, s, o);
    float mean = s * (1.0f / DIM);
    float d0 = f0.x - mean, d1 = f0.y - mean, d2 = f0.z - mean, d3 = f0.w - mean;
    float d4 = f1.x - mean, d5 = f1.y - mean, d6 = f1.z - mean, d7 = f1.w - mean;
    float vs = d0*d0 + d1*d1 + d2*d2 + d3*d3 + d4*d4 + d5*d5 + d6*d6 + d7*d7;
#pragma unroll
    for (int o = 16; o; o >>= 1) vs += __shfl_xor_sync(0xffffffffu, vs, o);
    float inv = rsqrtf(vs * (1.0f / DIM) + 1e-5f);
    const float4* g4 = (const float4*)g + lane * 2;
    const float4* b4 = (const float4*)b + lane * 2;
    float4 ga = __ldg(g4), gb = __ldg(g4 + 1);
    float4 ba = __ldg(b4), bb = __ldg(b4 + 1);
    __half2 o[4];
    o[0] = __floats2half2_rn(d0 * inv * ga.x + ba.x, d1 * inv * ga.y + ba.y);
    o[1] = __floats2half2_rn(d2 * inv * ga.z + ba.z, d3 * inv * ga.w + ba.w);
    o[2] = __floats2half2_rn(d4 * inv * gb.x + bb.x, d5 * inv * gb.y + bb.y);
    o[3] = __floats2half2_rn(d6 * inv * gb.z + bb.z, d7 * inv * gb.w + bb.w);
    *(uint4*)(Y + (long)row * DIM + lane * 8) = *(uint4*)o;
}

// ---------------- attention ----------------
#define ASTR 264
#define ATTN_SMEM (4 * 3 * 8 * ASTR * 2)

__global__ __launch_bounds__(256)
void attn_kernel(const __half* __restrict__ Q, long qb_stride,
                 const __half* __restrict__ KV, int koff,
                 __half* __restrict__ O) {
    extern __shared__ __half sm[];
    const int g = threadIdx.x >> 6;
    const int t = threadIdx.x & 63;
    const long b = (long)blockIdx.x * 4 + g;
    __half* Qs = sm + g * (3 * 8 * ASTR);
    __half* Ks = Qs + 8 * ASTR;
    __half* Vs = Ks + 8 * ASTR;
    const __half* qp  = Q + b * qb_stride;
    const __half* kvp = KV + b * 8 * KVW + koff;
#pragma unroll
    for (int i = t; i < 256; i += 64) {
        int r = i >> 5, c = (i & 31) * 8;
        *(uint4*)(Qs + r * ASTR + c) = *(const uint4*)(qp + r * 256 + c);
    }
#pragma unroll
    for (int i = t; i < 512; i += 64) {
        int r = i >> 6, c = (i & 63) * 8;
        __half* dst = (c < 256) ? (Ks + r * ASTR + c) : (Vs + r * ASTR + c - 256);
        *(uint4*)dst = *(const uint4*)(kvp + (long)r * KVW + c);
    }
    __syncthreads();
    const int q = t & 7, h = t >> 3, d0 = h * DHEAD;

    float qv[DHEAD];
    const __half2* qrow = (const __half2*)(Qs + q * ASTR + d0);
#pragma unroll
    for (int d2 = 0; d2 < 16; d2++) {
        float2 f = __half22float2(qrow[d2]);
        qv[2 * d2] = f.x; qv[2 * d2 + 1] = f.y;
    }
    float sc[8], mx = -1e30f;
#pragma unroll
    for (int k = 0; k < 8; k++) {
        const __half2* krow = (const __half2*)(Ks + k * ASTR + d0);
        float s = 0.f;
#pragma unroll
        for (int d2 = 0; d2 < 16; d2++) {
            float2 f = __half22float2(krow[d2]);
            s += qv[2 * d2] * f.x + qv[2 * d2 + 1] * f.y;
        }
        s *= 0.17677669529663687f;
        sc[k] = s; mx = fmaxf(mx, s);
    }
    float sum = 0.f;
#pragma unroll
    for (int k = 0; k < 8; k++) { sc[k] = __expf(sc[k] - mx); sum += sc[k]; }
    float inv = 1.0f / sum;
    float out[DHEAD];
#pragma unroll
    for (int d = 0; d < DHEAD; d++) out[d] = 0.f;
#pragma unroll
    for (int k = 0; k < 8; k++) {
        float p = sc[k] * inv;
        const __half2* vrow = (const __half2*)(Vs + k * ASTR + d0);
#pragma unroll
        for (int d2 = 0; d2 < 16; d2++) {
            float2 f = __half22float2(vrow[d2]);
            out[2 * d2]     += p * f.x;
            out[2 * d2 + 1] += p * f.y;
        }
    }
    __half2* op = (__half2*)(O + b * 2048 + q * 256 + d0);
#pragma unroll
    for (int d2 = 0; d2 < 16; d2++)
        op[d2] = __floats2half2_rn(out[2 * d2], out[2 * d2 + 1]);
}

// ---------------- host glue ----------------
static inline void launch_gemm(int mode, const __half* A, const __half* Bt, const float* bias,
                               float* C, __half* Ch, const int* rowmap, int M, int N, int K) {
    dim3 grid(N / BN, (M + BM - 1) / BM);
    switch (mode) {
    case 1: gemm_h<true,  false, false, true,  false, false><<<grid, 256, GSMEM>>>(A, Bt, bias, C, Ch, rowmap, M, N, K); break;
    case 2: gemm_h<false, true,  true,  false, false, false><<<grid, 256, GSMEM>>>(A, Bt, bias, C, Ch, rowmap, M, N, K); break;
    case 3: gemm_h<false, false, false, true,  false, false><<<grid, 256, GSMEM>>>(A, Bt, bias, C, Ch, rowmap, M, N, K); break;
    case 6: gemm_h<false, false, false, true,  true,  false><<<grid, 256, GSMEM>>>(A, Bt, bias, C, Ch, rowmap, M, N, K); break;
    case 4: gemm_h<false, true,  true,  true,  false, false><<<grid, 256, GSMEM>>>(A, Bt, bias, C, Ch, rowmap, M, N, K); break;
    case 5: gemm_h<false, false, true,  false, false, true ><<<grid, 256, GSMEM>>>(A, Bt, bias, C, Ch, rowmap, M, N, K); break;
    }
}

extern "C" void kernel_launch(void* const* d_in, const int* in_sizes, int n_in,
                              void* d_out, int out_size) {
    const float* x      = (const float*)d_in[0];
    const int*   linds  = (const int*)  d_in[1];
    const float* mlp_w  = (const float*)d_in[2];
    const float* mlp_b  = (const float*)d_in[3];
    const float* bg_tok = (const float*)d_in[4];
    const float* ln1_g  = (const float*)d_in[5];
    const float* ln1_b  = (const float*)d_in[6];
    const float* wq     = (const float*)d_in[7];
    const float* bq     = (const float*)d_in[8];
    const float* wk     = (const float*)d_in[9];
    const float* bk     = (const float*)d_in[10];
    const float* wv     = (const float*)d_in[11];
    const float* bv     = (const float*)d_in[12];
    const float* wo     = (const float*)d_in[13];
    const float* bo     = (const float*)d_in[14];
    const float* ln2_g  = (const float*)d_in[15];
    const float* ln2_b  = (const float*)d_in[16];
    const float* w1     = (const float*)d_in[17];
    const float* b1     = (const float*)d_in[18];
    const float* w2     = (const float*)d_in[19];
    const float* b2     = (const float*)d_in[20];
    const float* proj_w = (const float*)d_in[21];
    const float* proj_b = (const float*)d_in[22];
    float* out = (float*)d_out;

    __half *xh, *qh, *h2, *ctxh, *lnh, *Oh, *ffh, *trxh, *kvh, *wTh, *q0;
    float *trx, *bkv;
    int *dest, *cnt;
    cudaGetSymbolAddress((void**)&xh,   g_xh);
    cudaGetSymbolAddress((void**)&qh,   g_qh);
    cudaGetSymbolAddress((void**)&h2,   g_h2);
    cudaGetSymbolAddress((void**)&ctxh, g_ctxh);
    cudaGetSymbolAddress((void**)&lnh,  g_lnh);
    cudaGetSymbolAddress((void**)&Oh,   g_Oh);
    cudaGetSymbolAddress((void**)&ffh,  g_ffh);
    cudaGetSymbolAddress((void**)&trxh, g_trxh);
    cudaGetSymbolAddress((void**)&kvh,  g_kvh);
    cudaGetSymbolAddress((void**)&trx,  g_trx);
    cudaGetSymbolAddress((void**)&wTh,  g_wTh);
    cudaGetSymbolAddress((void**)&bkv,  g_bkv);
    cudaGetSymbolAddress((void**)&q0,   g_q0);
    cudaGetSymbolAddress((void**)&dest, g_dest);
    cudaGetSymbolAddress((void**)&cnt,  g_cnt);

    cudaFuncSetAttribute(gemm_h<true,  false, false, true,  false, false>, cudaFuncAttributeMaxDynamicSharedMemorySize, GSMEM);
    cudaFuncSetAttribute(gemm_h<false, true,  true,  false, false, false>, cudaFuncAttributeMaxDynamicSharedMemorySize, GSMEM);
    cudaFuncSetAttribute(gemm_h<false, false, false, true,  false, false>, cudaFuncAttributeMaxDynamicSharedMemorySize, GSMEM);
    cudaFuncSetAttribute(gemm_h<false, false, false, true,  true,  false>, cudaFuncAttributeMaxDynamicSharedMemorySize, GSMEM);
    cudaFuncSetAttribute(gemm_h<false, true,  true,  true,  false, false>, cudaFuncAttributeMaxDynamicSharedMemorySize, GSMEM);
    cudaFuncSetAttribute(gemm_h<false, false, true,  false, false, true >, cudaFuncAttributeMaxDynamicSharedMemorySize, GSMEM);
    cudaFuncSetAttribute(attn_kernel, cudaFuncAttributeMaxDynamicSharedMemorySize, ATTN_SMEM);

    transpose_all<<<7360, dim3(32, 8)>>>(mlp_w, wq, wk, wv, wo, w1, w2, proj_w, wTh);
    f2h_kernel<<<(NOBS * DIM / 4 + 255) / 256, 256>>>(x, xh, (long)NOBS * DIM);
    bkv_kernel<<<(DEPTH * 512 + 255) / 256, 256>>>(bk, bv, bkv);

    launch_gemm(1, xh, wTh + OFF_MLP + 0 * 65536, mlp_b + 0 * DIM, nullptr, qh, nullptr, M_PAD, DIM, DIM);
    launch_gemm(1, qh, wTh + OFF_MLP + 1 * 65536, mlp_b + 1 * DIM, nullptr, h2, nullptr, M_PAD, DIM, DIM);

    zero_cnt_kernel<<<(NB + 255) / 256, 256>>>(cnt);
    dest_kernel<<<(M_PAD + 255) / 256, 256>>>(linds, cnt, dest);
    launch_gemm(6, h2, wTh + OFF_MLP + 2 * 65536, mlp_b + 2 * DIM, nullptr, ctxh, dest, M_PAD, DIM, DIM);

    init_trx_kernel<<<NOBS, DIM>>>(bg_tok, trx);
    q0_kernel<<<LMAX, DIM>>>(bg_tok, ln1_g, ln1_b, wTh + OFF_WQ, bq, q0);

    launch_gemm(3, ctxh, wTh + OFF_WKV, bkv, nullptr, kvh, nullptr, M_PAD, KVW, DIM);

    for (int l = 0; l < DEPTH; l++) {
        const long o256 = (long)l * 65536;
        if (l == 0) {
            attn_kernel<<<NB / 4, 256, ATTN_SMEM>>>(q0, 0, kvh, 0, Oh);
        } else {
            ln_kernel<<<NOBS / 8, 256>>>(trx, ln1_g + l * DIM, ln1_b + l * DIM, lnh, NOBS);
            launch_gemm(3, lnh, wTh + OFF_WQ + o256, bq + l * DIM, nullptr, qh, nullptr, M_PAD, DIM, DIM);
            attn_kernel<<<NB / 4, 256, ATTN_SMEM>>>(qh, 2048, kvh, l * 512, Oh);
        }
        launch_gemm(2, Oh, wTh + OFF_WO + o256, bo + l * DIM, trx, nullptr, nullptr, M_PAD, DIM, DIM);
        ln_kernel<<<NOBS / 8, 256>>>(trx, ln2_g + l * DIM, ln2_b + l * DIM, lnh, NOBS);
        launch_gemm(1, lnh, wTh + OFF_W1 + (long)l * 262144, b1 + l * FF, nullptr, ffh, nullptr, M_PAD, FF, DIM);
        if (l < DEPTH - 1)
            launch_gemm(2, ffh, wTh + OFF_W2 + (long)l * 262144, b2 + l * DIM, trx, nullptr, nullptr, M_PAD, DIM, FF);
        else
            launch_gemm(4, ffh, wTh + OFF_W2 + (long)l * 262144, b2 + l * DIM, trx, trxh, nullptr, M_PAD, DIM, FF);
    }

    launch_gemm(5, trxh, wTh + OFF_PROJ, proj_b, out, nullptr, nullptr, NB, CL, OUTD);
}

// round 17
// speedup vs baseline: 1.0319x; 1.0129x over previous
#include <cuda_runtime.h>
#include <cuda_fp16.h>
#include <cstdint>

// ---------------- problem dims ----------------
#define NOBS   72000
#define M_PAD  72064
#define NB     9000
#define LMAX   8
#define DIM    256
#define HEADS  8
#define DHEAD  32
#define DEPTH  8
#define FF     1024
#define OUTD   2048
#define CL     512
#define KVW    4096

// ---------------- scratch ----------------
__device__ __half g_xh  [M_PAD * DIM];
__device__ __half g_qh  [M_PAD * DIM];
__device__ __half g_h2  [M_PAD * DIM];
__device__ __half g_ctxh[M_PAD * DIM];
__device__ __half g_lnh [M_PAD * DIM];
__device__ __half g_Oh  [M_PAD * DIM];
__device__ __half g_ffh [M_PAD * FF];
__device__ __half g_trxh[M_PAD * DIM];
__device__ __half g_kvh [(long)M_PAD * KVW];
__device__ float  g_trx [M_PAD * DIM];
__device__ __half g_wTh [7536640];
__device__ float  g_bkv [DEPTH * 512];
__device__ __half g_q0  [LMAX * DIM];
__device__ int    g_dest[M_PAD];
__device__ int    g_cnt [NB];

#define OFF_MLP  0
#define OFF_WQ   196608
#define OFF_WKV  720896
#define OFF_WO   1769472
#define OFF_W1   2293760
#define OFF_W2   4390912
#define OFF_PROJ 6488064

// ---------------- helpers ----------------
__device__ __forceinline__ uint32_t smem_u32(const void* p) {
    uint32_t a;
    asm("{ .reg .u64 t; cvta.to.shared.u64 t, %1; cvt.u32.u64 %0, t; }" : "=r"(a) : "l"(p));
    return a;
}
__device__ __forceinline__ float gelu_tanh(float x) {
    const float k0 = 0.7978845608028654f, k1 = 0.044715f;
    float t = k0 * (x + k1 * x * x * x);
    float th;
    asm("tanh.approx.f32 %0, %1;" : "=f"(th) : "f"(t));
    return 0.5f * x * (1.0f + th);
}
__device__ __forceinline__ void ldm_x4(uint32_t* r, uint32_t addr) {
    asm volatile("ldmatrix.sync.aligned.m8n8.x4.shared.b16 {%0,%1,%2,%3}, [%4];"
        : "=r"(r[0]), "=r"(r[1]), "=r"(r[2]), "=r"(r[3]) : "r"(addr));
}
__device__ __forceinline__ void mma_f16(float* d, const uint32_t* a, const uint32_t* b) {
    asm volatile("mma.sync.aligned.m16n8k16.row.col.f32.f16.f16.f32 "
        "{%0,%1,%2,%3}, {%4,%5,%6,%7}, {%8,%9}, {%0,%1,%2,%3};"
        : "+f"(d[0]), "+f"(d[1]), "+f"(d[2]), "+f"(d[3])
        : "r"(a[0]), "r"(a[1]), "r"(a[2]), "r"(a[3]), "r"(b[0]), "r"(b[1]));
}
__device__ __forceinline__ void cp16(uint32_t dst, const void* src) {
    asm volatile("cp.async.cg.shared.global [%0], [%1], 16;"
        :: "r"(dst), "l"(src) : "memory");
}
#define CP_COMMIT() asm volatile("cp.async.commit_group;" ::: "memory")
#define CP_WAIT1()  asm volatile("cp.async.wait_group 1;" ::: "memory")
#define SWZ(off) ((off) ^ (((off) >> 3) & 0x70))

// ---------------- setup kernels ----------------
__global__ void zero_cnt_kernel(int* cnt) {
    int i = blockIdx.x * 256 + threadIdx.x;
    if (i < NB) cnt[i] = 0;
}
__global__ void dest_kernel(const int* __restrict__ li, int* __restrict__ cnt,
                            int* __restrict__ dest) {
    int i = blockIdx.x * 256 + threadIdx.x;
    if (i >= M_PAD) return;
    if (i >= NOBS) { dest[i] = i; return; }
    int f = li[3*i] * 1800 + li[3*i+1] * 60 + li[3*i+2];
    int slot = atomicAdd(&cnt[f], 1);
    dest[i] = f * LMAX + slot;
}
__global__ void f2h_kernel(const float* __restrict__ in, __half* __restrict__ out, long n) {
    long i = ((long)blockIdx.x * 256 + threadIdx.x) * 4;
    if (i >= n) return;
    float4 v = *(const float4*)(in + i);
    *(__half2*)(out + i)     = __floats2half2_rn(v.x, v.y);
    *(__half2*)(out + i + 2) = __floats2half2_rn(v.z, v.w);
}
__global__ void bkv_kernel(const float* __restrict__ bk, const float* __restrict__ bv,
                           float* __restrict__ bkv) {
    int i = blockIdx.x * 256 + threadIdx.x;
    if (i >= DEPTH * 512) return;
    int l = i >> 9, c = i & 511;
    bkv[i] = (c < 256) ? bk[l * 256 + c] : bv[l * 256 + c - 256];
}

// layer-0 Q shortcut
__global__ void q0_kernel(const float* __restrict__ bg, const float* __restrict__ g,
                          const float* __restrict__ b, const __half* __restrict__ wqT0,
                          const float* __restrict__ bq0, __half* __restrict__ q0) {
    __shared__ float row[DIM];
    __shared__ float red[8];
    const int tok = blockIdx.x, tid = threadIdx.x;
    const int lane = tid & 31, wid = tid >> 5;
    float x = bg[tok * DIM + tid];
    float s = x;
#pragma unroll
    for (int o = 16; o; o >>= 1) s += __shfl_xor_sync(0xffffffffu, s, o);
    if (lane == 0) red[wid] = s;
    __syncthreads();
    if (wid == 0) {
        float t = (lane < 8) ? red[lane] : 0.f;
#pragma unroll
        for (int o = 4; o; o >>= 1) t += __shfl_xor_sync(0xffffffffu, t, o);
        if (lane == 0) red[0] = t;
    }
    __syncthreads();
    float mean = red[0] * (1.0f / DIM);
    float d = x - mean, vs = d * d;
#pragma unroll
    for (int o = 16; o; o >>= 1) vs += __shfl_xor_sync(0xffffffffu, vs, o);
    if (lane == 0) red[wid] = vs;
    __syncthreads();
    if (wid == 0) {
        float t = (lane < 8) ? red[lane] : 0.f;
#pragma unroll
        for (int o = 4; o; o >>= 1) t += __shfl_xor_sync(0xffffffffu, t, o);
        if (lane == 0) red[0] = t;
    }
    __syncthreads();
    float inv = rsqrtf(red[0] * (1.0f / DIM) + 1e-5f);
    row[tid] = __half2float(__float2half_rn(d * inv * g[tid] + b[tid]));
    __syncthreads();
    float acc = 0.f;
    const __half* wrow = wqT0 + tid * DIM;
#pragma unroll 8
    for (int k = 0; k < DIM; k++) acc += row[k] * __half2float(wrow[k]);
    q0[tok * DIM + tid] = __float2half_rn(acc + bq0[tid]);
}

// ---------------- single-launch fused weight transpose ----------------
__global__ __launch_bounds__(256)
void transpose_all(const float* __restrict__ mlp_w, const float* __restrict__ wq,
                   const float* __restrict__ wk,    const float* __restrict__ wv,
                   const float* __restrict__ wo,    const float* __restrict__ w1,
                   const float* __restrict__ w2,    const float* __restrict__ projw,
                   __half* __restrict__ wTh) {
    __shared__ float tile[32][33];
    const int tb = blockIdx.x;
    const float* src; __half* dst; int R, C, tiles_x, rem;
    if (tb < 192)       { int s=tb/64;        rem=tb%64;  src=mlp_w+s*65536;  dst=wTh+OFF_MLP+s*65536;  R=256;  C=256;  tiles_x=8;  }
    else if (tb < 704)  { int s=(tb-192)/64;  rem=(tb-192)%64;  src=wq+s*65536; dst=wTh+OFF_WQ+s*65536; R=256; C=256; tiles_x=8; }
    else if (tb < 1216) { int s=(tb-704)/64;  rem=(tb-704)%64;  src=wk+s*65536; dst=wTh+OFF_WKV+(long)s*131072;        R=256; C=256; tiles_x=8; }
    else if (tb < 1728) { int s=(tb-1216)/64; rem=(tb-1216)%64; src=wv+s*65536; dst=wTh+OFF_WKV+65536+(long)s*131072;  R=256; C=256; tiles_x=8; }
    else if (tb < 2240) { int s=(tb-1728)/64; rem=(tb-1728)%64; src=wo+s*65536; dst=wTh+OFF_WO+s*65536; R=256; C=256; tiles_x=8; }
    else if (tb < 4288) { int s=(tb-2240)/256; rem=(tb-2240)%256; src=w1+(long)s*262144; dst=wTh+OFF_W1+(long)s*262144; R=256;  C=1024; tiles_x=32; }
    else if (tb < 6336) { int s=(tb-4288)/256; rem=(tb-4288)%256; src=w2+(long)s*262144; dst=wTh+OFF_W2+(long)s*262144; R=1024; C=256;  tiles_x=8;  }
    else                { rem=tb-6336; src=projw; dst=wTh+OFF_PROJ; R=2048; C=512; tiles_x=16; }
    const int ty = rem / tiles_x, tx = rem % tiles_x;
    const int c0 = tx * 32, r0 = ty * 32;
    for (int i = threadIdx.y; i < 32; i += 8)
        tile[i][threadIdx.x] = src[(long)(r0 + i) * C + c0 + threadIdx.x];
    __syncthreads();
    for (int i = threadIdx.y; i < 32; i += 8)
        dst[(long)(c0 + i) * R + r0 + threadIdx.x] = __float2half_rn(tile[threadIdx.x][i]);
}

// ---------------- fp16 tensor-core GEMM (R14 config + RESB broadcast-residual) ----------------
#define BM 128
#define BN 128
#define BKH 64
#define STG_BYTES 32768
#define GSMEM (3 * STG_BYTES)
#define EP_STRIDE 136

template<bool GELU, bool RES, bool RESB, bool F32O, bool HO, bool SCAT, bool GUARD>
__global__ __launch_bounds__(256, 2)
void gemm_h(const __half* __restrict__ A, const __half* __restrict__ Bt,
            const float* __restrict__ bias, float* __restrict__ C,
            __half* __restrict__ Ch, const int* __restrict__ rowmap,
            const float* __restrict__ bres, int M, int N, int K) {
    extern __shared__ char smem[];
    const uint32_t sb = smem_u32(smem);
    const int tid = threadIdx.x;
    const int lane = tid & 31, wid = tid >> 5;
    const int warpM = wid >> 2, warpN = wid & 3;
    const int m0 = blockIdx.y * BM, n0 = blockIdx.x * BN;
    const int ntiles = K / BKH;

    float acc[4][4][4];
#pragma unroll
    for (int i = 0; i < 4; i++)
#pragma unroll
        for (int j = 0; j < 4; j++)
#pragma unroll
            for (int k = 0; k < 4; k++) acc[i][j][k] = 0.0f;

    const int lrow = tid >> 3, lcc = tid & 7;
    auto issue = [&](uint32_t abase, int kt) {
        const int kb = kt * BKH;
        const uint32_t bbase = abase + 16384;
        const __half* asrc = A + (long)(m0 + lrow) * K + kb + lcc * 8;
        const __half* bsrc = Bt + (long)(n0 + lrow) * K + kb + lcc * 8;
#pragma unroll
        for (int i = 0; i < 4; i++)
            cp16(abase + SWZ((lrow + 32 * i) * 128 + lcc * 16), asrc + (long)(32 * i) * K);
#pragma unroll
        for (int i = 0; i < 4; i++)
            cp16(bbase + SWZ((lrow + 32 * i) * 128 + lcc * 16), bsrc + (long)(32 * i) * K);
    };

    issue(sb, 0); CP_COMMIT();
    issue(sb + STG_BYTES, 1); CP_COMMIT();

    const int lm = lane >> 3, lr = lane & 7;

    uint32_t cstage = sb;
    uint32_t istage = sb + 2 * STG_BYTES;
    for (int kt = 0; kt < ntiles; kt++) {
        CP_WAIT1();
        __syncthreads();
        if (kt + 2 < ntiles) issue(istage, kt + 2);
        CP_COMMIT();
        const uint32_t abase = cstage;
        const uint32_t bbase = cstage + 16384;
        istage = cstage;
        cstage = (cstage == sb + 2 * STG_BYTES) ? sb : cstage + STG_BYTES;
#pragma unroll
        for (int ks = 0; ks < 4; ks++) {
            const int k0 = ks * 16;
            uint32_t afr[4][4], bfr[2][4];
#pragma unroll
            for (int mt = 0; mt < 4; mt++) {
                int row = warpM * 64 + mt * 16 + (lm & 1) * 8 + lr;
                int colh = k0 + (lm >> 1) * 8;
                ldm_x4(afr[mt], abase + SWZ(row * 128 + colh * 2));
            }
#pragma unroll
            for (int nt = 0; nt < 2; nt++) {
                int row = warpN * 32 + nt * 16 + (lm & 1) * 8 + lr;
                int colh = k0 + (lm >> 1) * 8;
                ldm_x4(bfr[nt], bbase + SWZ(row * 128 + colh * 2));
            }
#pragma unroll
            for (int mt = 0; mt < 4; mt++)
#pragma unroll
                for (int j = 0; j < 4; j++) {
                    uint32_t b2[2] = { bfr[j >> 1][j & 1], bfr[j >> 1][(j & 1) + 2] };
                    mma_f16(acc[mt][j], afr[mt], b2);
                }
        }
    }

    const int g = lane >> 2, t = lane & 3;
    __half* stg = (__half*)smem;
    if (HO) __syncthreads();

#pragma unroll
    for (int j = 0; j < 4; j++) {
        const int col = n0 + warpN * 32 + j * 8 + t * 2;
        const float bx = __ldg(&bias[col]), by = __ldg(&bias[col + 1]);
#pragma unroll
        for (int mt = 0; mt < 4; mt++) {
#pragma unroll
            for (int h = 0; h < 2; h++) {
                int lrowm = warpM * 64 + mt * 16 + g + h * 8;
                int row = m0 + lrowm;
                if (GUARD && row >= M) continue;
                float v0 = acc[mt][j][2 * h + 0] + bx;
                float v1 = acc[mt][j][2 * h + 1] + by;
                if (GELU) { v0 = gelu_tanh(v0); v1 = gelu_tanh(v1); }
                if (RES) {
                    int orow = SCAT ? rowmap[row] : row;
                    float2 r = *(const float2*)(C + (long)orow * N + col);
                    v0 += r.x; v1 += r.y;
                    if (F32O) {
                        float2 o; o.x = v0; o.y = v1;
                        *(float2*)(C + (long)orow * N + col) = o;
                    }
                } else if (RESB) {
                    // broadcast residual: tiny [8, N] table, row = token id
                    float2 r = *(const float2*)(bres + (row & 7) * N + col);
                    v0 += r.x; v1 += r.y;
                    if (F32O) {
                        float2 o; o.x = v0; o.y = v1;
                        *(float2*)(C + (long)row * N + col) = o;
                    }
                } else if (F32O) {
                    int orow = SCAT ? rowmap[row] : row;
                    float2 o; o.x = v0; o.y = v1;
                    *(float2*)(C + (long)orow * N + col) = o;
                }
                if (HO)
                    *(__half2*)&stg[lrowm * EP_STRIDE + warpN * 32 + j * 8 + t * 2] =
                        __floats2half2_rn(v0, v1);
            }
        }
    }

    if (HO) {
        __syncthreads();
#pragma unroll
        for (int it = 0; it < 8; it++) {
            int job = it * 256 + tid;
            int row = job >> 4, chunk = job & 15;
            int grow = m0 + row;
            if (GUARD && grow >= M) continue;
            int orow = SCAT ? rowmap[grow] : grow;
            uint4 v = *(uint4*)&stg[row * EP_STRIDE + chunk * 8];
            *(uint4*)(Ch + (long)orow * N + n0 + chunk * 8) = v;
        }
    }
}

// ---------------- LayerNorm: vectorized ----------------
__global__ void ln_kernel(const float* __restrict__ X, const float* __restrict__ g,
                          const float* __restrict__ b, __half* __restrict__ Y, int M) {
    int row = blockIdx.x * 8 + (threadIdx.x >> 5);
    int lane = threadIdx.x & 31;
    if (row >= M) return;
    const float4* x4 = (const float4*)(X + (long)row * DIM) + lane * 2;
    float4 f0 = x4[0], f1 = x4[1];
    float s = f0.x + f0.y + f0.z + f0.w + f1.x + f1.y + f1.z + f1.w;
#pragma unroll
    for (int o = 16; o; o >>= 1) s += __shfl_xor_sync(0xffffffffu, s, o);
    float mean = s * (1.0f / DIM);
    float d0 = f0.x - mean, d1 = f0.y - mean, d2 = f0.z - mean, d3 = f0.w - mean;
    float d4 = f1.x - mean, d5 = f1.y - mean, d6 = f1.z - mean, d7 = f1.w - mean;
    float vs = d0*d0 + d1*d1 + d2*d2 + d3*d3 + d4*d4 + d5*d5 + d6*d6 + d7*d7;
#pragma unroll
    for (int o = 16; o; o >>= 1) vs += __shfl_xor_sync(0xffffffffu, vs, o);
    float inv = rsqrtf(vs * (1.0f / DIM) + 1e-5f);
    const float4* g4 = (const float4*)g + lane * 2;
    const float4* b4 = (const float4*)b + lane * 2;
    float4 ga = __ldg(g4), gb = __ldg(g4 + 1);
    float4 ba = __ldg(b4), bb = __ldg(b4 + 1);
    __half2 o[4];
    o[0] = __floats2half2_rn(d0 * inv * ga.x + ba.x, d1 * inv * ga.y + ba.y);
    o[1] = __floats2half2_rn(d2 * inv * ga.z + ba.z, d3 * inv * ga.w + ba.w);
    o[2] = __floats2half2_rn(d4 * inv * gb.x + bb.x, d5 * inv * gb.y + bb.y);
    o[3] = __floats2half2_rn(d6 * inv * gb.z + bb.z, d7 * inv * gb.w + bb.w);
    *(uint4*)(Y + (long)row * DIM + lane * 8) = *(uint4*)o;
}

// ---------------- attention ----------------
#define ASTR 264
#define ATTN_SMEM (4 * 3 * 8 * ASTR * 2)

__global__ __launch_bounds__(256)
void attn_kernel(const __half* __restrict__ Q, long qb_stride,
                 const __half* __restrict__ KV, int koff,
                 __half* __restrict__ O) {
    extern __shared__ __half sm[];
    const int g = threadIdx.x >> 6;
    const int t = threadIdx.x & 63;
    const long b = (long)blockIdx.x * 4 + g;
    __half* Qs = sm + g * (3 * 8 * ASTR);
    __half* Ks = Qs + 8 * ASTR;
    __half* Vs = Ks + 8 * ASTR;
    const __half* qp  = Q + b * qb_stride;
    const __half* kvp = KV + b * 8 * KVW + koff;
#pragma unroll
    for (int i = t; i < 256; i += 64) {
        int r = i >> 5, c = (i & 31) * 8;
        *(uint4*)(Qs + r * ASTR + c) = *(const uint4*)(qp + r * 256 + c);
    }
#pragma unroll
    for (int i = t; i < 512; i += 64) {
        int r = i >> 6, c = (i & 63) * 8;
        __half* dst = (c < 256) ? (Ks + r * ASTR + c) : (Vs + r * ASTR + c - 256);
        *(uint4*)dst = *(const uint4*)(kvp + (long)r * KVW + c);
    }
    __syncthreads();
    const int q = t & 7, h = t >> 3, d0 = h * DHEAD;

    float qv[DHEAD];
    const __half2* qrow = (const __half2*)(Qs + q * ASTR + d0);
#pragma unroll
    for (int d2 = 0; d2 < 16; d2++) {
        float2 f = __half22float2(qrow[d2]);
        qv[2 * d2] = f.x; qv[2 * d2 + 1] = f.y;
    }
    float sc[8], mx = -1e30f;
#pragma unroll
    for (int k = 0; k < 8; k++) {
        const __half2* krow = (const __half2*)(Ks + k * ASTR + d0);
        float s = 0.f;
#pragma unroll
        for (int d2 = 0; d2 < 16; d2++) {
            float2 f = __half22float2(krow[d2]);
            s += qv[2 * d2] * f.x + qv[2 * d2 + 1] * f.y;
        }
        s *= 0.17677669529663687f;
        sc[k] = s; mx = fmaxf(mx, s);
    }
    float sum = 0.f;
#pragma unroll
    for (int k = 0; k < 8; k++) { sc[k] = __expf(sc[k] - mx); sum += sc[k]; }
    float inv = 1.0f / sum;
    float out[DHEAD];
#pragma unroll
    for (int d = 0; d < DHEAD; d++) out[d] = 0.f;
#pragma unroll
    for (int k = 0; k < 8; k++) {
        float p = sc[k] * inv;
        const __half2* vrow = (const __half2*)(Vs + k * ASTR + d0);
#pragma unroll
        for (int d2 = 0; d2 < 16; d2++) {
            float2 f = __half22float2(vrow[d2]);
            out[2 * d2]     += p * f.x;
            out[2 * d2 + 1] += p * f.y;
        }
    }
    __half2* op = (__half2*)(O + b * 2048 + q * 256 + d0);
#pragma unroll
    for (int d2 = 0; d2 < 16; d2++)
        op[d2] = __floats2half2_rn(out[2 * d2], out[2 * d2 + 1]);
}

// ---------------- host glue ----------------
// 1 gelu,h-out | 2 res,f32 | 3 h-out | 6 h-out+scatter | 4 res,f32+h-out
// 5 f32+guard (proj) | 7 bcast-res,f32 (layer-0 WO)
static inline void launch_gemm(int mode, const __half* A, const __half* Bt, const float* bias,
                               float* C, __half* Ch, const int* rowmap, const float* bres,
                               int M, int N, int K) {
    dim3 grid(N / BN, (M + BM - 1) / BM);
    switch (mode) {
    case 1: gemm_h<true,  false, false, false, true,  false, false><<<grid, 256, GSMEM>>>(A, Bt, bias, C, Ch, rowmap, bres, M, N, K); break;
    case 2: gemm_h<false, true,  false, true,  false, false, false><<<grid, 256, GSMEM>>>(A, Bt, bias, C, Ch, rowmap, bres, M, N, K); break;
    case 3: gemm_h<false, false, false, false, true,  false, false><<<grid, 256, GSMEM>>>(A, Bt, bias, C, Ch, rowmap, bres, M, N, K); break;
    case 6: gemm_h<false, false, false, false, true,  true,  false><<<grid, 256, GSMEM>>>(A, Bt, bias, C, Ch, rowmap, bres, M, N, K); break;
    case 4: gemm_h<false, true,  false, true,  true,  false, false><<<grid, 256, GSMEM>>>(A, Bt, bias, C, Ch, rowmap, bres, M, N, K); break;
    case 5: gemm_h<false, false, false, true,  false, false, true ><<<grid, 256, GSMEM>>>(A, Bt, bias, C, Ch, rowmap, bres, M, N, K); break;
    case 7: gemm_h<false, false, true,  true,  false, false, false><<<grid, 256, GSMEM>>>(A, Bt, bias, C, Ch, rowmap, bres, M, N, K); break;
    }
}

extern "C" void kernel_launch(void* const* d_in, const int* in_sizes, int n_in,
                              void* d_out, int out_size) {
    const float* x      = (const float*)d_in[0];
    const int*   linds  = (const int*)  d_in[1];
    const float* mlp_w  = (const float*)d_in[2];
    const float* mlp_b  = (const float*)d_in[3];
    const float* bg_tok = (const float*)d_in[4];
    const float* ln1_g  = (const float*)d_in[5];
    const float* ln1_b  = (const float*)d_in[6];
    const float* wq     = (const float*)d_in[7];
    const float* bq     = (const float*)d_in[8];
    const float* wk     = (const float*)d_in[9];
    const float* bk     = (const float*)d_in[10];
    const float* wv     = (const float*)d_in[11];
    const float* bv     = (const float*)d_in[12];
    const float* wo     = (const float*)d_in[13];
    const float* bo     = (const float*)d_in[14];
    const float* ln2_g  = (const float*)d_in[15];
    const float* ln2_b  = (const float*)d_in[16];
    const float* w1     = (const float*)d_in[17];
    const float* b1     = (const float*)d_in[18];
    const float* w2     = (const float*)d_in[19];
    const float* b2     = (const float*)d_in[20];
    const float* proj_w = (const float*)d_in[21];
    const float* proj_b = (const float*)d_in[22];
    float* out = (float*)d_out;

    __half *xh, *qh, *h2, *ctxh, *lnh, *Oh, *ffh, *trxh, *kvh, *wTh, *q0;
    float *trx, *bkv;
    int *dest, *cnt;
    cudaGetSymbolAddress((void**)&xh,   g_xh);
    cudaGetSymbolAddress((void**)&qh,   g_qh);
    cudaGetSymbolAddress((void**)&h2,   g_h2);
    cudaGetSymbolAddress((void**)&ctxh, g_ctxh);
    cudaGetSymbolAddress((void**)&lnh,  g_lnh);
    cudaGetSymbolAddress((void**)&Oh,   g_Oh);
    cudaGetSymbolAddress((void**)&ffh,  g_ffh);
    cudaGetSymbolAddress((void**)&trxh, g_trxh);
    cudaGetSymbolAddress((void**)&kvh,  g_kvh);
    cudaGetSymbolAddress((void**)&trx,  g_trx);
    cudaGetSymbolAddress((void**)&wTh,  g_wTh);
    cudaGetSymbolAddress((void**)&bkv,  g_bkv);
    cudaGetSymbolAddress((void**)&q0,   g_q0);
    cudaGetSymbolAddress((void**)&dest, g_dest);
    cudaGetSymbolAddress((void**)&cnt,  g_cnt);

    cudaFuncSetAttribute(gemm_h<true,  false, false, false, true,  false, false>, cudaFuncAttributeMaxDynamicSharedMemorySize, GSMEM);
    cudaFuncSetAttribute(gemm_h<false, true,  false, true,  false, false, false>, cudaFuncAttributeMaxDynamicSharedMemorySize, GSMEM);
    cudaFuncSetAttribute(gemm_h<false, false, false, false, true,  false, false>, cudaFuncAttributeMaxDynamicSharedMemorySize, GSMEM);
    cudaFuncSetAttribute(gemm_h<false, false, false, false, true,  true,  false>, cudaFuncAttributeMaxDynamicSharedMemorySize, GSMEM);
    cudaFuncSetAttribute(gemm_h<false, true,  false, true,  true,  false, false>, cudaFuncAttributeMaxDynamicSharedMemorySize, GSMEM);
    cudaFuncSetAttribute(gemm_h<false, false, false, true,  false, false, true >, cudaFuncAttributeMaxDynamicSharedMemorySize, GSMEM);
    cudaFuncSetAttribute(gemm_h<false, false, true,  true,  false, false, false>, cudaFuncAttributeMaxDynamicSharedMemorySize, GSMEM);
    cudaFuncSetAttribute(attn_kernel, cudaFuncAttributeMaxDynamicSharedMemorySize, ATTN_SMEM);

    transpose_all<<<7360, dim3(32, 8)>>>(mlp_w, wq, wk, wv, wo, w1, w2, proj_w, wTh);
    f2h_kernel<<<(NOBS * DIM / 4 + 255) / 256, 256>>>(x, xh, (long)NOBS * DIM);
    bkv_kernel<<<(DEPTH * 512 + 255) / 256, 256>>>(bk, bv, bkv);

    launch_gemm(1, xh, wTh + OFF_MLP + 0 * 65536, mlp_b + 0 * DIM, nullptr, qh, nullptr, nullptr, M_PAD, DIM, DIM);
    launch_gemm(1, qh, wTh + OFF_MLP + 1 * 65536, mlp_b + 1 * DIM, nullptr, h2, nullptr, nullptr, M_PAD, DIM, DIM);

    zero_cnt_kernel<<<(NB + 255) / 256, 256>>>(cnt);
    dest_kernel<<<(M_PAD + 255) / 256, 256>>>(linds, cnt, dest);
    launch_gemm(6, h2, wTh + OFF_MLP + 2 * 65536, mlp_b + 2 * DIM, nullptr, ctxh, dest, nullptr, M_PAD, DIM, DIM);

    q0_kernel<<<LMAX, DIM>>>(bg_tok, ln1_g, ln1_b, wTh + OFF_WQ, bq, q0);

    launch_gemm(3, ctxh, wTh + OFF_WKV, bkv, nullptr, kvh, nullptr, nullptr, M_PAD, KVW, DIM);

    for (int l = 0; l < DEPTH; l++) {
        const long o256 = (long)l * 65536;
        if (l == 0) {
            attn_kernel<<<NB / 4, 256, ATTN_SMEM>>>(q0, 0, kvh, 0, Oh);
            // layer-0 WO: residual = broadcast bg_tok (replaces init_trx + big read)
            launch_gemm(7, Oh, wTh + OFF_WO, bo, trx, nullptr, nullptr, bg_tok, M_PAD, DIM, DIM);
        } else {
            ln_kernel<<<NOBS / 8, 256>>>(trx, ln1_g + l * DIM, ln1_b + l * DIM, lnh, NOBS);
            launch_gemm(3, lnh, wTh + OFF_WQ + o256, bq + l * DIM, nullptr, qh, nullptr, nullptr, M_PAD, DIM, DIM);
            attn_kernel<<<NB / 4, 256, ATTN_SMEM>>>(qh, 2048, kvh, l * 512, Oh);
            launch_gemm(2, Oh, wTh + OFF_WO + o256, bo + l * DIM, trx, nullptr, nullptr, nullptr, M_PAD, DIM, DIM);
        }
        ln_kernel<<<NOBS / 8, 256>>>(trx, ln2_g + l * DIM, ln2_b + l * DIM, lnh, NOBS);
        launch_gemm(1, lnh, wTh + OFF_W1 + (long)l * 262144, b1 + l * FF, nullptr, ffh, nullptr, nullptr, M_PAD, FF, DIM);
        if (l < DEPTH - 1)
            launch_gemm(2, ffh, wTh + OFF_W2 + (long)l * 262144, b2 + l * DIM, trx, nullptr, nullptr, nullptr, M_PAD, DIM, FF);
        else
            launch_gemm(4, ffh, wTh + OFF_W2 + (long)l * 262144, b2 + l * DIM, trx, trxh, nullptr, nullptr, M_PAD, DIM, FF);
    }

    launch_gemm(5, trxh, wTh + OFF_PROJ, proj_b, out, nullptr, nullptr, nullptr, NB, CL, OUTD);
}